// round 14
// baseline (speedup 1.0000x reference)
#include <cuda_runtime.h>
#include <cuda_fp16.h>
#include <cstdint>

// ---------------- problem constants ----------------
#define T     2048
#define DIN   512
#define DOUT  512
#define KF    24
#define NC    48
#define KU    3
#define NT    256
#define SPLANES 8

// gemm2 schedule: 296 blocks, heavy tiles first (2 dynamic waves at 1 CTA/SM)
__constant__ int c_SP[16]  = {1, 2, 2, 3, 3, 3, 4, 4, 5, 5, 6, 6, 7, 7, 8, 8};
__constant__ int c_OFF[16] = {292, 284, 276, 264, 252, 240, 224, 208,
                              188, 168, 144, 120, 92, 64, 32, 0};
#define GRID2 296

// ---------------- device scratch ----------------
// Z in paired-B-fragment layout: uint4 idx = ((c*64+tc)*64 + nfrag)*32 + lane
__device__ uint4    g_ZF[(size_t)NC * 64 * 64 * 32];    // 100 MB
__device__ float    g_part[(size_t)SPLANES * T * DOUT]; // split-K partials
__device__ __half   g_phiH[NC * T];                     // minus channel has (-1)^lag baked in
__device__ uint32_t g_ToepF[(size_t)NC * 16 * 4 * 2048];// A-frag Toeplitz, 25 MB
__device__ uint32_t g_xF[(size_t)KU * 16 * 16 * 2048];  // A-frag shifted x (AR), 6 MB
__device__ uint32_t g_WF[(size_t)NC * 4 * 16 * 2048];   // A-frag weights, 25 MB
__device__ uint4    g_xBF[(size_t)16 * 256 * 32];       // paired-B-frag x (gemm1), 2 MB
__device__ uint4    g_MF[(size_t)KU * 16 * 64 * 32];    // paired-B-frag AR weights, 1.5 MB
__device__ __half   g_xh[(size_t)T * DIN];              // x fp16 (for prep_rest)

// ---------------- helpers ----------------
__device__ __forceinline__ void mma168(float* c, const uint32_t* a, const uint32_t* b) {
    asm volatile("mma.sync.aligned.m16n8k16.row.col.f32.f16.f16.f32 "
        "{%0,%1,%2,%3}, {%4,%5,%6,%7}, {%8,%9}, {%0,%1,%2,%3};"
        : "+f"(c[0]), "+f"(c[1]), "+f"(c[2]), "+f"(c[3])
        : "r"(a[0]), "r"(a[1]), "r"(a[2]), "r"(a[3]), "r"(b[0]), "r"(b[1]));
}

// A-frag index u (0..2047) -> (m 0..127, k 0..31); layout [m16][kf][lane][reg]
__device__ __forceinline__ void frag_decode(int u, int& m, int& k) {
    int reg = u & 3, lane = (u >> 2) & 31, kf = (u >> 7) & 1, m16 = (u >> 8) & 7;
    m = m16 * 16 + (reg & 1) * 8 + (lane >> 2);
    k = kf * 16 + (reg >> 1) * 8 + (lane & 3) * 2;
}

// ---------------- prep stage 1: coalesced staging of x(fp16) and phiT(fp16) ----------------
__global__ void prep_h(const float* __restrict__ x, const float* __restrict__ phi) {
    int idx = blockIdx.x * 256 + threadIdx.x;
    if (idx < T * DIN) g_xh[idx] = __float2half_rn(x[idx]);
    int p = idx - T * DIN;
    if (p >= 0 && p < NC * T) {
        int c = p / T, s = p - c * T;
        int k = (c < KF) ? c : c - KF;
        float v = phi[s * KF + k];
        if (c >= KF && (s & 1)) v = -v;
        g_phiH[p] = __float2half_rn(v);
    }
}

// ---------------- prep stage 2: all fragment packing, one launch ----------------
// blocks: [0,768) toepF | [768,1536) xF | [1536,4608) wf | [4608,5120) xbf | [5120,5504) mf
__global__ void prep_rest(const float* __restrict__ x, const float* __restrict__ M,
                          const float* __restrict__ Mp, const float* __restrict__ Mm) {
    __shared__ float s[32][129];
    const int bb = blockIdx.x;
    const int tid = threadIdx.x;
    const __half z = __float2half_rn(0.f);

    if (bb < 768) {
        int c = bb >> 4, d = bb & 15;
        const __half* ph = g_phiH + c * T;
        __half2* dst = reinterpret_cast<__half2*>(g_ToepF + (size_t)bb * 8192);
        for (int u0 = tid; u0 < 8192; u0 += 256) {
            int ks = u0 >> 11, u = u0 & 2047;
            int m, k; frag_decode(u, m, k);
            int i0 = d * 128 + m - (ks * 32 + k);
            __half v0 = (i0 >= 0)     ? ph[i0]     : z;
            __half v1 = (i0 - 1 >= 0) ? ph[i0 - 1] : z;
            dst[u0] = __halves2half2(v0, v1);
        }
    } else if (bb < 1536) {
        int b = bb - 768;
        int ksc = b & 15, ti = (b >> 4) & 15, tau = b >> 8;
        __half2* dst = reinterpret_cast<__half2*>(g_xF + (size_t)b * 2048);
        for (int u = tid; u < 2048; u += 256) {
            int m, k; frag_decode(u, m, k);
            int row = ti * 128 + m - tau;
            __half v0 = z, v1 = z;
            if (row >= 0) {
                v0 = g_xh[(size_t)row * DIN + ksc * 32 + k];
                v1 = g_xh[(size_t)row * DIN + ksc * 32 + k + 1];
            }
            dst[u] = __halves2half2(v0, v1);
        }
    } else if (bb < 4608) {
        int b = bb - 1536;
        int ksc = b & 15, by = (b >> 4) & 3, c = b >> 6;
        const float* W = (c < KF) ? Mp + (size_t)c * DIN * DOUT
                                  : Mm + (size_t)(c - KF) * DIN * DOUT;
        int o0 = by * 128, d0 = ksc * 32;
        for (int e = tid; e < 32 * 128; e += 256) {
            int dd = e >> 7, oo = e & 127;
            s[dd][oo] = W[(size_t)(d0 + dd) * DOUT + o0 + oo];
        }
        __syncthreads();
        __half2* dst = reinterpret_cast<__half2*>(g_WF + (size_t)b * 2048);
        for (int u = tid; u < 2048; u += 256) {
            int m, k; frag_decode(u, m, k);
            dst[u] = __halves2half2(__float2half_rn(s[k][m]), __float2half_rn(s[k + 1][m]));
        }
    } else if (bb < 5120) {
        int idx = (bb - 4608) * 256 + tid;
        int lane = idx & 31, tfrag = (idx >> 5) & 255, ksc = idx >> 13;
        int t = tfrag * 8 + (lane >> 2);
        uint32_t comp[4];
        #pragma unroll
        for (int cI = 0; cI < 4; ++cI) {
            int kf = cI >> 1, reg = cI & 1;
            int d = ksc * 32 + kf * 16 + reg * 8 + (lane & 3) * 2;
            __half2 v = __floats2half2_rn(x[(size_t)t * DIN + d], x[(size_t)t * DIN + d + 1]);
            comp[cI] = *reinterpret_cast<uint32_t*>(&v);
        }
        g_xBF[idx] = make_uint4(comp[0], comp[1], comp[2], comp[3]);
    } else {
        int idx = (bb - 5120) * 256 + tid;
        int lane = idx & 31, nfrag = (idx >> 5) & 63, ksc = (idx >> 11) & 15, tau = idx >> 15;
        int o = nfrag * 8 + (lane >> 2);
        uint32_t comp[4];
        #pragma unroll
        for (int cI = 0; cI < 4; ++cI) {
            int kf = cI >> 1, reg = cI & 1;
            int d = ksc * 32 + kf * 16 + reg * 8 + (lane & 3) * 2;
            __half2 v = __floats2half2_rn(M[((size_t)o * DIN + d) * KU + tau],
                                          M[((size_t)o * DIN + d + 1) * KU + tau]);
            comp[cI] = *reinterpret_cast<uint32_t*>(&v);
        }
        g_MF[idx] = make_uint4(comp[0], comp[1], comp[2], comp[3]);
    }
}

// ------- GEMM1: all-register-direct; writes Z in paired-B-frag layout (unchanged) -------
__global__ void __launch_bounds__(NT, 2) gemm1_kernel() {
    const int tid = threadIdx.x;
    const int warp = tid >> 5, lane = tid & 31;
    const int mbase = (warp >> 2) * 64, nbase = (warp & 3) * 32;
    const int m16b = mbase >> 4;
    const int tx = blockIdx.x, by = blockIdx.y, c = blockIdx.z;
    const int o0 = by * 128;

    const uint4* abase = reinterpret_cast<const uint4*>(g_WF) + (size_t)(c * 4 + by) * 16 * 512;
    const int tf0 = tx * 16 + (nbase >> 3);

    float acc[4][4][4];
    #pragma unroll
    for (int i = 0; i < 4; ++i)
        #pragma unroll
        for (int j = 0; j < 4; ++j)
            #pragma unroll
            for (int e = 0; e < 4; ++e) acc[i][j][e] = 0.f;

    uint4 areg[2][4];
    uint4 breg[4];
    auto loadA = [&](int ksc) {
        const uint4* ap = abase + ksc * 512;
        #pragma unroll
        for (int kf = 0; kf < 2; ++kf)
            #pragma unroll
            for (int mf = 0; mf < 4; ++mf)
                areg[kf][mf] = ap[(m16b + mf) * 64 + kf * 32 + lane];
    };
    auto loadB = [&](int ksc) {
        #pragma unroll
        for (int nf = 0; nf < 4; ++nf)
            breg[nf] = g_xBF[(size_t)(ksc * 256 + tf0 + nf) * 32 + lane];
    };

    loadA(0); loadB(0);
    for (int k = 0; k < 16; k++) {
        #pragma unroll
        for (int kf = 0; kf < 2; ++kf)
            #pragma unroll
            for (int mf = 0; mf < 4; ++mf)
                #pragma unroll
                for (int nf = 0; nf < 4; ++nf)
                    mma168(acc[mf][nf], reinterpret_cast<const uint32_t*>(&areg[kf][mf]),
                           reinterpret_cast<const uint32_t*>(&breg[nf]) + kf * 2);
        if (k + 1 < 16) { loadA(k + 1); loadB(k + 1); }
    }

    const int tc = tx * 4 + (warp & 3);
    #pragma unroll
    for (int mf = 0; mf < 4; ++mf) {
        int nfr = (o0 + mbase + mf * 16) >> 3;
        uint32_t lo[4], hi[4];
        #pragma unroll
        for (int nf = 0; nf < 4; ++nf) {
            __half2 l = __floats2half2_rn(acc[mf][nf][0], acc[mf][nf][1]);
            __half2 h = __floats2half2_rn(acc[mf][nf][2], acc[mf][nf][3]);
            lo[nf] = *reinterpret_cast<uint32_t*>(&l);
            hi[nf] = *reinterpret_cast<uint32_t*>(&h);
        }
        g_ZF[(size_t)((c * 64 + tc) * 64 + nfr) * 32 + lane]     = make_uint4(lo[0], lo[1], lo[2], lo[3]);
        g_ZF[(size_t)((c * 64 + tc) * 64 + nfr + 1) * 32 + lane] = make_uint4(hi[0], hi[1], hi[2], hi[3]);
    }
}

// -- GEMM2: double-buffered operands, 1 CTA/SM (255-reg budget), incremental decode --
__global__ void __launch_bounds__(NT, 1) gemm2_kernel() {
    const int tid = threadIdx.x;
    const int warp = tid >> 5, lane = tid & 31;
    const int lg = lane >> 2, t4 = lane & 3;
    const int mbase = (warp >> 2) * 64, nbase = (warp & 3) * 32;
    const int m16b = mbase >> 4;

    const int bx = (int)blockIdx.x;
    int i = 15;
    #pragma unroll
    for (int ii = 0; ii < 16; ++ii)
        if (bx >= c_OFF[ii] && bx < c_OFF[ii] + 4 * c_SP[ii]) i = ii;
    const int w = bx - c_OFF[i];
    const int SP = c_SP[i];
    const int ot = w % 4, sp = w / 4;
    const int t0 = i * 128, o0 = ot * 128;
    const int per = (i + 1) * 4, nconv = NC * per, ntot = nconv + KU * (DIN / 32);
    const int NCH = (ntot - sp + SP - 1) / SP;
    const int nfr0 = (o0 >> 3) + (nbase >> 3);

    float acc[4][4][4];
    #pragma unroll
    for (int a0 = 0; a0 < 4; ++a0)
        #pragma unroll
        for (int b0 = 0; b0 < 4; ++b0)
            #pragma unroll
            for (int e = 0; e < 4; ++e) acc[a0][b0][e] = 0.f;

    // incremental chunk state (one division per block)
    int q = sp;
    int cch = sp / per;
    int rm = sp - cch * per;

    uint4 aA[2][4], aB[2][4];   // double-buffered A (two kf halves each)
    uint4 bA[4],    bB[4];      // double-buffered B

    auto loadInto = [&](uint4 (&Ar)[2][4], uint4 (&Br)[4]) {
        const uint4* ap;
        const uint4* bp;
        if (q < nconv) {
            int j = rm >> 2, ks = rm & 3;
            ap = reinterpret_cast<const uint4*>(g_ToepF) +
                 (size_t)((cch * 16 + (i - j)) * 4 + ks) * 512;
            bp = g_ZF + (size_t)((cch * 64 + j * 4 + ks) * 64 + nfr0) * 32;
        } else {
            int r = q - nconv, tau = r >> 4, ksc = r & 15;
            ap = reinterpret_cast<const uint4*>(g_xF) +
                 (size_t)((tau * 16 + i) * 16 + ksc) * 512;
            bp = g_MF + (size_t)((tau * 16 + ksc) * 64 + nfr0) * 32;
        }
        #pragma unroll
        for (int kf = 0; kf < 2; ++kf)
            #pragma unroll
            for (int mf = 0; mf < 4; ++mf)
                Ar[kf][mf] = ap[(m16b + mf) * 64 + kf * 32 + lane];
        #pragma unroll
        for (int nf = 0; nf < 4; ++nf)
            Br[nf] = bp[(size_t)nf * 32 + lane];
        q += SP;
        rm += SP;
        if (rm >= per) { rm -= per; cch++; }
    };
    auto mmaFrom = [&](const uint4 (&Ar)[2][4], const uint4 (&Br)[4]) {
        #pragma unroll
        for (int kf = 0; kf < 2; ++kf)
            #pragma unroll
            for (int mf = 0; mf < 4; ++mf)
                #pragma unroll
                for (int nf = 0; nf < 4; ++nf)
                    mma168(acc[mf][nf], reinterpret_cast<const uint32_t*>(&Ar[kf][mf]),
                           reinterpret_cast<const uint32_t*>(&Br[nf]) + kf * 2);
    };

    loadInto(aA, bA);
    for (int k = 0; k < NCH; k += 2) {
        if (k + 1 < NCH) loadInto(aB, bB);   // loads issue before MMAs; independent
        mmaFrom(aA, bA);
        if (k + 1 < NCH) {
            if (k + 2 < NCH) loadInto(aA, bA);
            mmaFrom(aB, bB);
        }
    }

    float* P = g_part + (size_t)sp * T * DOUT;
    #pragma unroll
    for (int mf = 0; mf < 4; ++mf) {
        int r0 = t0 + mbase + mf * 16 + lg;
        #pragma unroll
        for (int nf = 0; nf < 4; ++nf) {
            int cc = o0 + nbase + nf * 8 + 2 * t4;
            *(float2*)(P + (size_t)r0 * DOUT + cc)       = make_float2(acc[mf][nf][0], acc[mf][nf][1]);
            *(float2*)(P + (size_t)(r0 + 8) * DOUT + cc) = make_float2(acc[mf][nf][2], acc[mf][nf][3]);
        }
    }
}

// ---------------- reduce split-K partials (tile i has c_SP[i] planes) ----------------
__global__ void reduce_kernel(float* __restrict__ out) {
    size_t idx = (size_t)(blockIdx.x * blockDim.x + threadIdx.x) * 4;
    int t = (int)(idx / DOUT);
    int np = c_SP[t >> 7];
    float4 s = make_float4(0.f, 0.f, 0.f, 0.f);
    for (int p = 0; p < np; ++p) {
        float4 v = *(const float4*)(g_part + (size_t)p * T * DOUT + idx);
        s.x += v.x; s.y += v.y; s.z += v.z; s.w += v.w;
    }
    *(float4*)(out + idx) = s;
}

// ---------------- entry ----------------
extern "C" void kernel_launch(void* const* d_in, const int* in_sizes, int n_in,
                              void* d_out, int out_size) {
    const float* x   = (const float*)d_in[0];
    const float* phi = (const float*)d_in[1];
    const float* M   = (const float*)d_in[2];
    const float* Mp  = (const float*)d_in[3];
    const float* Mm  = (const float*)d_in[4];
    float* out = (float*)d_out;

    prep_h<<<(T * DIN + NC * T + 255) / 256, 256>>>(x, phi);
    prep_rest<<<5504, NT>>>(x, M, Mp, Mm);
    gemm1_kernel<<<dim3(16, 4, NC), NT>>>();
    gemm2_kernel<<<GRID2, NT>>>();
    reduce_kernel<<<(T * DOUT / 4 + 255) / 256, 256>>>(out);
}

// round 15
// speedup vs baseline: 1.1548x; 1.1548x over previous
#include <cuda_runtime.h>
#include <cuda_fp16.h>
#include <cstdint>

// ---------------- problem constants ----------------
#define T     2048
#define DIN   512
#define DOUT  512
#define KF    24
#define NC    48
#define KU    3
#define NT    256
#define SPLANES 8

// gemm2 one-wave schedule for 2 CTAs/SM: 296 blocks
__constant__ int c_SP[16]  = {1, 2, 2, 3, 3, 3, 4, 4, 5, 5, 6, 6, 7, 7, 8, 8};
__constant__ int c_OFF[16] = {292, 284, 276, 264, 252, 240, 224, 208,
                              188, 168, 144, 120, 92, 64, 32, 0};
#define GRID2 296

// ---------------- device scratch ----------------
// Z in paired-B-fragment layout: uint4 idx = ((c*64+tc)*64 + nfrag)*32 + lane
__device__ uint4    g_ZF[(size_t)NC * 64 * 64 * 32];    // 100 MB
__device__ float    g_part[(size_t)SPLANES * T * DOUT]; // split-K partials
__device__ __half   g_phiH[NC * T];                     // minus channel has (-1)^lag baked in
__device__ uint32_t g_ToepF[(size_t)NC * 16 * 4 * 2048];// A-frag Toeplitz, 25 MB
__device__ uint32_t g_xF[(size_t)KU * 16 * 16 * 2048];  // A-frag shifted x (AR), 6 MB
__device__ uint32_t g_WF[(size_t)NC * 4 * 16 * 2048];   // A-frag weights, 25 MB
__device__ uint4    g_xBF[(size_t)16 * 256 * 32];       // paired-B-frag x (gemm1), 2 MB
__device__ uint4    g_MF[(size_t)KU * 16 * 64 * 32];    // paired-B-frag AR weights, 1.5 MB
__device__ __half   g_xh[(size_t)T * DIN];              // x fp16 (for prep_rest)

// ---------------- helpers ----------------
__device__ __forceinline__ void mma168(float* c, const uint32_t* a, const uint32_t* b) {
    asm volatile("mma.sync.aligned.m16n8k16.row.col.f32.f16.f16.f32 "
        "{%0,%1,%2,%3}, {%4,%5,%6,%7}, {%8,%9}, {%0,%1,%2,%3};"
        : "+f"(c[0]), "+f"(c[1]), "+f"(c[2]), "+f"(c[3])
        : "r"(a[0]), "r"(a[1]), "r"(a[2]), "r"(a[3]), "r"(b[0]), "r"(b[1]));
}
__device__ __forceinline__ void pfL1(const void* p) {
    asm volatile("prefetch.global.L1 [%0];" :: "l"(p));
}

// A-frag index u (0..2047) -> (m 0..127, k 0..31); layout [m16][kf][lane][reg]
__device__ __forceinline__ void frag_decode(int u, int& m, int& k) {
    int reg = u & 3, lane = (u >> 2) & 31, kf = (u >> 7) & 1, m16 = (u >> 8) & 7;
    m = m16 * 16 + (reg & 1) * 8 + (lane >> 2);
    k = kf * 16 + (reg >> 1) * 8 + (lane & 3) * 2;
}

// ---------------- prep stage 1: coalesced staging of x(fp16) and phiT(fp16) ----------------
__global__ void prep_h(const float* __restrict__ x, const float* __restrict__ phi) {
    int idx = blockIdx.x * 256 + threadIdx.x;
    if (idx < T * DIN) g_xh[idx] = __float2half_rn(x[idx]);
    int p = idx - T * DIN;
    if (p >= 0 && p < NC * T) {
        int c = p / T, s = p - c * T;
        int k = (c < KF) ? c : c - KF;
        float v = phi[s * KF + k];
        if (c >= KF && (s & 1)) v = -v;
        g_phiH[p] = __float2half_rn(v);
    }
}

// ---------------- prep stage 2: all fragment packing, one launch ----------------
// blocks: [0,768) toepF | [768,1536) xF | [1536,4608) wf | [4608,5120) xbf | [5120,5504) mf
__global__ void prep_rest(const float* __restrict__ x, const float* __restrict__ M,
                          const float* __restrict__ Mp, const float* __restrict__ Mm) {
    __shared__ float s[32][129];
    const int bb = blockIdx.x;
    const int tid = threadIdx.x;
    const __half z = __float2half_rn(0.f);

    if (bb < 768) {
        int c = bb >> 4, d = bb & 15;
        const __half* ph = g_phiH + c * T;
        __half2* dst = reinterpret_cast<__half2*>(g_ToepF + (size_t)bb * 8192);
        for (int u0 = tid; u0 < 8192; u0 += 256) {
            int ks = u0 >> 11, u = u0 & 2047;
            int m, k; frag_decode(u, m, k);
            int i0 = d * 128 + m - (ks * 32 + k);
            __half v0 = (i0 >= 0)     ? ph[i0]     : z;
            __half v1 = (i0 - 1 >= 0) ? ph[i0 - 1] : z;
            dst[u0] = __halves2half2(v0, v1);
        }
    } else if (bb < 1536) {
        int b = bb - 768;
        int ksc = b & 15, ti = (b >> 4) & 15, tau = b >> 8;
        __half2* dst = reinterpret_cast<__half2*>(g_xF + (size_t)b * 2048);
        for (int u = tid; u < 2048; u += 256) {
            int m, k; frag_decode(u, m, k);
            int row = ti * 128 + m - tau;
            __half v0 = z, v1 = z;
            if (row >= 0) {
                v0 = g_xh[(size_t)row * DIN + ksc * 32 + k];
                v1 = g_xh[(size_t)row * DIN + ksc * 32 + k + 1];
            }
            dst[u] = __halves2half2(v0, v1);
        }
    } else if (bb < 4608) {
        int b = bb - 1536;
        int ksc = b & 15, by = (b >> 4) & 3, c = b >> 6;
        const float* W = (c < KF) ? Mp + (size_t)c * DIN * DOUT
                                  : Mm + (size_t)(c - KF) * DIN * DOUT;
        int o0 = by * 128, d0 = ksc * 32;
        for (int e = tid; e < 32 * 128; e += 256) {
            int dd = e >> 7, oo = e & 127;
            s[dd][oo] = W[(size_t)(d0 + dd) * DOUT + o0 + oo];
        }
        __syncthreads();
        __half2* dst = reinterpret_cast<__half2*>(g_WF + (size_t)b * 2048);
        for (int u = tid; u < 2048; u += 256) {
            int m, k; frag_decode(u, m, k);
            dst[u] = __halves2half2(__float2half_rn(s[k][m]), __float2half_rn(s[k + 1][m]));
        }
    } else if (bb < 5120) {
        int idx = (bb - 4608) * 256 + tid;
        int lane = idx & 31, tfrag = (idx >> 5) & 255, ksc = idx >> 13;
        int t = tfrag * 8 + (lane >> 2);
        uint32_t comp[4];
        #pragma unroll
        for (int cI = 0; cI < 4; ++cI) {
            int kf = cI >> 1, reg = cI & 1;
            int d = ksc * 32 + kf * 16 + reg * 8 + (lane & 3) * 2;
            __half2 v = __floats2half2_rn(x[(size_t)t * DIN + d], x[(size_t)t * DIN + d + 1]);
            comp[cI] = *reinterpret_cast<uint32_t*>(&v);
        }
        g_xBF[idx] = make_uint4(comp[0], comp[1], comp[2], comp[3]);
    } else {
        int idx = (bb - 5120) * 256 + tid;
        int lane = idx & 31, nfrag = (idx >> 5) & 63, ksc = (idx >> 11) & 15, tau = idx >> 15;
        int o = nfrag * 8 + (lane >> 2);
        uint32_t comp[4];
        #pragma unroll
        for (int cI = 0; cI < 4; ++cI) {
            int kf = cI >> 1, reg = cI & 1;
            int d = ksc * 32 + kf * 16 + reg * 8 + (lane & 3) * 2;
            __half2 v = __floats2half2_rn(M[((size_t)o * DIN + d) * KU + tau],
                                          M[((size_t)o * DIN + d + 1) * KU + tau]);
            comp[cI] = *reinterpret_cast<uint32_t*>(&v);
        }
        g_MF[idx] = make_uint4(comp[0], comp[1], comp[2], comp[3]);
    }
}

// ------- GEMM1: all-register-direct; writes Z in paired-B-frag layout (unchanged) -------
__global__ void __launch_bounds__(NT, 2) gemm1_kernel() {
    const int tid = threadIdx.x;
    const int warp = tid >> 5, lane = tid & 31;
    const int mbase = (warp >> 2) * 64, nbase = (warp & 3) * 32;
    const int m16b = mbase >> 4;
    const int tx = blockIdx.x, by = blockIdx.y, c = blockIdx.z;
    const int o0 = by * 128;

    const uint4* abase = reinterpret_cast<const uint4*>(g_WF) + (size_t)(c * 4 + by) * 16 * 512;
    const int tf0 = tx * 16 + (nbase >> 3);

    float acc[4][4][4];
    #pragma unroll
    for (int i = 0; i < 4; ++i)
        #pragma unroll
        for (int j = 0; j < 4; ++j)
            #pragma unroll
            for (int e = 0; e < 4; ++e) acc[i][j][e] = 0.f;

    uint4 areg[2][4];
    uint4 breg[4];
    auto loadA = [&](int ksc) {
        const uint4* ap = abase + ksc * 512;
        #pragma unroll
        for (int kf = 0; kf < 2; ++kf)
            #pragma unroll
            for (int mf = 0; mf < 4; ++mf)
                areg[kf][mf] = ap[(m16b + mf) * 64 + kf * 32 + lane];
    };
    auto loadB = [&](int ksc) {
        #pragma unroll
        for (int nf = 0; nf < 4; ++nf)
            breg[nf] = g_xBF[(size_t)(ksc * 256 + tf0 + nf) * 32 + lane];
    };

    loadA(0); loadB(0);
    for (int k = 0; k < 16; k++) {
        #pragma unroll
        for (int kf = 0; kf < 2; ++kf)
            #pragma unroll
            for (int mf = 0; mf < 4; ++mf)
                #pragma unroll
                for (int nf = 0; nf < 4; ++nf)
                    mma168(acc[mf][nf], reinterpret_cast<const uint32_t*>(&areg[kf][mf]),
                           reinterpret_cast<const uint32_t*>(&breg[nf]) + kf * 2);
        if (k + 1 < 16) { loadA(k + 1); loadB(k + 1); }
    }

    const int tc = tx * 4 + (warp & 3);
    #pragma unroll
    for (int mf = 0; mf < 4; ++mf) {
        int nfr = (o0 + mbase + mf * 16) >> 3;
        uint32_t lo[4], hi[4];
        #pragma unroll
        for (int nf = 0; nf < 4; ++nf) {
            __half2 l = __floats2half2_rn(acc[mf][nf][0], acc[mf][nf][1]);
            __half2 h = __floats2half2_rn(acc[mf][nf][2], acc[mf][nf][3]);
            lo[nf] = *reinterpret_cast<uint32_t*>(&l);
            hi[nf] = *reinterpret_cast<uint32_t*>(&h);
        }
        g_ZF[(size_t)((c * 64 + tc) * 64 + nfr) * 32 + lane]     = make_uint4(lo[0], lo[1], lo[2], lo[3]);
        g_ZF[(size_t)((c * 64 + tc) * 64 + nfr + 1) * 32 + lane] = make_uint4(hi[0], hi[1], hi[2], hi[3]);
    }
}

// -- GEMM2: R13 structure + L1 prefetch of the upcoming chunk (no extra buffering) --
__global__ void __launch_bounds__(NT, 2) gemm2_kernel() {
    const int tid = threadIdx.x;
    const int warp = tid >> 5, lane = tid & 31;
    const int lg = lane >> 2, t4 = lane & 3;
    const int mbase = (warp >> 2) * 64, nbase = (warp & 3) * 32;
    const int m16b = mbase >> 4;

    const int bx = (int)blockIdx.x;
    int i = 15;
    #pragma unroll
    for (int ii = 0; ii < 16; ++ii)
        if (bx >= c_OFF[ii] && bx < c_OFF[ii] + 4 * c_SP[ii]) i = ii;
    const int w = bx - c_OFF[i];
    const int SP = c_SP[i];
    const int ot = w % 4, sp = w / 4;
    const int t0 = i * 128, o0 = ot * 128;
    const int per = (i + 1) * 4, nconv = NC * per, ntot = nconv + KU * (DIN / 32);
    const int NCH = (ntot - sp + SP - 1) / SP;
    const int nfr0 = (o0 >> 3) + (nbase >> 3);

    float acc[4][4][4];
    #pragma unroll
    for (int a0 = 0; a0 < 4; ++a0)
        #pragma unroll
        for (int b0 = 0; b0 < 4; ++b0)
            #pragma unroll
            for (int e = 0; e < 4; ++e) acc[a0][b0][e] = 0.f;

    // incremental chunk state (one division per block)
    int q = sp;
    int cch = sp / per;
    int rm = sp - cch * per;

    uint4 areg[2][4];
    uint4 breg[4];
    auto chunkPtrs = [&](const uint4*& ap, const uint4*& bp) {
        if (q < nconv) {
            int j = rm >> 2, ks = rm & 3;
            ap = reinterpret_cast<const uint4*>(g_ToepF) +
                 (size_t)((cch * 16 + (i - j)) * 4 + ks) * 512;
            bp = g_ZF + (size_t)((cch * 64 + j * 4 + ks) * 64 + nfr0) * 32;
        } else {
            int r = q - nconv, tau = r >> 4, ksc = r & 15;
            ap = reinterpret_cast<const uint4*>(g_xF) +
                 (size_t)((tau * 16 + i) * 16 + ksc) * 512;
            bp = g_MF + (size_t)((tau * 16 + ksc) * 64 + nfr0) * 32;
        }
    };
    auto advance = [&]() {
        q += SP;
        rm += SP;
        if (rm >= per) { rm -= per; cch++; }
    };
    auto loadChunk = [&]() {
        const uint4* ap;
        const uint4* bp;
        chunkPtrs(ap, bp);
        #pragma unroll
        for (int kf = 0; kf < 2; ++kf)
            #pragma unroll
            for (int mf = 0; mf < 4; ++mf)
                areg[kf][mf] = ap[(m16b + mf) * 64 + kf * 32 + lane];
        #pragma unroll
        for (int nf = 0; nf < 4; ++nf)
            breg[nf] = bp[(size_t)nf * 32 + lane];
        advance();
        // L1-prefetch the NEXT chunk's regions (warp covers 4KB A / 2KB B at line stride)
        if (q < ntot) {
            const uint4* pa;
            const uint4* pb;
            chunkPtrs(pa, pb);
            pfL1(pa + m16b * 64 + lane * 8);
            pfL1(pb + (lane & 15) * 8);
        }
    };

    loadChunk();
    for (int k = 0; k < NCH; k++) {
        #pragma unroll
        for (int kf = 0; kf < 2; ++kf)
            #pragma unroll
            for (int mf = 0; mf < 4; ++mf)
                #pragma unroll
                for (int nf = 0; nf < 4; ++nf)
                    mma168(acc[mf][nf], reinterpret_cast<const uint32_t*>(&areg[kf][mf]),
                           reinterpret_cast<const uint32_t*>(&breg[nf]) + kf * 2);
        if (k + 1 < NCH) loadChunk();
    }

    float* P = g_part + (size_t)sp * T * DOUT;
    #pragma unroll
    for (int mf = 0; mf < 4; ++mf) {
        int r0 = t0 + mbase + mf * 16 + lg;
        #pragma unroll
        for (int nf = 0; nf < 4; ++nf) {
            int cc = o0 + nbase + nf * 8 + 2 * t4;
            *(float2*)(P + (size_t)r0 * DOUT + cc)       = make_float2(acc[mf][nf][0], acc[mf][nf][1]);
            *(float2*)(P + (size_t)(r0 + 8) * DOUT + cc) = make_float2(acc[mf][nf][2], acc[mf][nf][3]);
        }
    }
}

// ---------------- reduce split-K partials (tile i has c_SP[i] planes) ----------------
__global__ void reduce_kernel(float* __restrict__ out) {
    size_t idx = (size_t)(blockIdx.x * blockDim.x + threadIdx.x) * 4;
    int t = (int)(idx / DOUT);
    int np = c_SP[t >> 7];
    float4 s = make_float4(0.f, 0.f, 0.f, 0.f);
    for (int p = 0; p < np; ++p) {
        float4 v = *(const float4*)(g_part + (size_t)p * T * DOUT + idx);
        s.x += v.x; s.y += v.y; s.z += v.z; s.w += v.w;
    }
    *(float4*)(out + idx) = s;
}

// ---------------- entry ----------------
extern "C" void kernel_launch(void* const* d_in, const int* in_sizes, int n_in,
                              void* d_out, int out_size) {
    const float* x   = (const float*)d_in[0];
    const float* phi = (const float*)d_in[1];
    const float* M   = (const float*)d_in[2];
    const float* Mp  = (const float*)d_in[3];
    const float* Mm  = (const float*)d_in[4];
    float* out = (float*)d_out;

    prep_h<<<(T * DIN + NC * T + 255) / 256, 256>>>(x, phi);
    prep_rest<<<5504, NT>>>(x, M, Mp, Mm);
    gemm1_kernel<<<dim3(16, 4, NC), NT>>>();
    gemm2_kernel<<<GRID2, NT>>>();
    reduce_kernel<<<(T * DOUT / 4 + 255) / 256, 256>>>(out);
}

// round 16
// speedup vs baseline: 1.1652x; 1.0090x over previous
#include <cuda_runtime.h>
#include <cuda_fp16.h>
#include <cstdint>

// ---------------- problem constants ----------------
#define T     2048
#define DIN   512
#define DOUT  512
#define KF    24
#define NC    48
#define KU    3
#define NT    256
#define SPLANES 8

// gemm2 one-wave schedule for 2 CTAs/SM: 296 blocks (minimax-optimal for sum=74)
__constant__ int c_SP[16]  = {1, 2, 2, 3, 3, 3, 4, 4, 5, 5, 6, 6, 7, 7, 8, 8};
__constant__ int c_OFF[16] = {292, 284, 276, 264, 252, 240, 224, 208,
                              188, 168, 144, 120, 92, 64, 32, 0};
#define GRID2 296

// ---------------- device scratch ----------------
// Z in paired-B-fragment layout: uint4 idx = ((c*64+tc)*64 + nfrag)*32 + lane
__device__ uint4    g_ZF[(size_t)NC * 64 * 64 * 32];    // 100 MB
__device__ float    g_part[(size_t)SPLANES * T * DOUT]; // split-K partials
__device__ uint32_t g_ToepF[(size_t)NC * 16 * 4 * 2048];// A-frag Toeplitz, 25 MB
__device__ uint32_t g_xF[(size_t)KU * 16 * 16 * 2048];  // A-frag shifted x (AR), 6 MB
__device__ uint32_t g_WF[(size_t)NC * 4 * 16 * 2048];   // A-frag weights, 25 MB
__device__ uint4    g_xBF[(size_t)16 * 256 * 32];       // paired-B-frag x (gemm1), 2 MB
__device__ uint4    g_MF[(size_t)KU * 16 * 64 * 32];    // paired-B-frag AR weights, 1.5 MB

// ---------------- helpers ----------------
__device__ __forceinline__ void mma168(float* c, const uint32_t* a, const uint32_t* b) {
    asm volatile("mma.sync.aligned.m16n8k16.row.col.f32.f16.f16.f32 "
        "{%0,%1,%2,%3}, {%4,%5,%6,%7}, {%8,%9}, {%0,%1,%2,%3};"
        : "+f"(c[0]), "+f"(c[1]), "+f"(c[2]), "+f"(c[3])
        : "r"(a[0]), "r"(a[1]), "r"(a[2]), "r"(a[3]), "r"(b[0]), "r"(b[1]));
}
__device__ __forceinline__ void pfL1(const void* p) {
    asm volatile("prefetch.global.L1 [%0];" :: "l"(p));
}

// A-frag index u (0..2047) -> (m 0..127, k 0..31); layout [m16][kf][lane][reg]
__device__ __forceinline__ void frag_decode(int u, int& m, int& k) {
    int reg = u & 3, lane = (u >> 2) & 31, kf = (u >> 7) & 1, m16 = (u >> 8) & 7;
    m = m16 * 16 + (reg & 1) * 8 + (lane >> 2);
    k = kf * 16 + (reg >> 1) * 8 + (lane & 3) * 2;
}

// phi with minus-channel sign baked in (identical rounding to prior prep_h path)
__device__ __forceinline__ __half phv(const float* __restrict__ phi, int c, int s) {
    int k = (c < KF) ? c : c - KF;
    float v = phi[s * KF + k];
    if (c >= KF && (s & 1)) v = -v;
    return __float2half_rn(v);
}

// ---------------- fused prep (single launch) ----------------
// blocks: [0,768) toepF | [768,1536) xF | [1536,4608) wf | [4608,5120) xbf | [5120,5504) mf
__global__ void prep_all(const float* __restrict__ x, const float* __restrict__ phi,
                         const float* __restrict__ M,
                         const float* __restrict__ Mp, const float* __restrict__ Mm) {
    __shared__ float s[32][129];
    const int bb = blockIdx.x;
    const int tid = threadIdx.x;
    const __half z = __float2half_rn(0.f);

    if (bb < 768) {
        // Toeplitz A-frags: (c,diag,ks): (m,k) = phi_c[diag*128 + m - (ks*32+k)]
        int c = bb >> 4, d = bb & 15;
        __half2* dst = reinterpret_cast<__half2*>(g_ToepF + (size_t)bb * 8192);
        for (int u0 = tid; u0 < 8192; u0 += 256) {
            int ks = u0 >> 11, u = u0 & 2047;
            int m, k; frag_decode(u, m, k);
            int i0 = d * 128 + m - (ks * 32 + k);
            __half v0 = (i0 >= 0)     ? phv(phi, c, i0)     : z;
            __half v1 = (i0 - 1 >= 0) ? phv(phi, c, i0 - 1) : z;
            dst[u0] = __halves2half2(v0, v1);
        }
    } else if (bb < 1536) {
        // shifted-x A-frags (AR): (tau,i,ksc): (m,k) = x[i*128+m-tau][ksc*32+k]
        int b = bb - 768;
        int ksc = b & 15, ti = (b >> 4) & 15, tau = b >> 8;
        __half2* dst = reinterpret_cast<__half2*>(g_xF + (size_t)b * 2048);
        for (int u = tid; u < 2048; u += 256) {
            int m, k; frag_decode(u, m, k);
            int row = ti * 128 + m - tau;
            __half v0 = z, v1 = z;
            if (row >= 0) {
                v0 = __float2half_rn(x[(size_t)row * DIN + ksc * 32 + k]);
                v1 = __float2half_rn(x[(size_t)row * DIN + ksc * 32 + k + 1]);
            }
            dst[u] = __halves2half2(v0, v1);
        }
    } else if (bb < 4608) {
        // weight A-frags: (c,oTile,ksc): (m,k) = W_c[d=ksc*32+k][o=oTile*128+m]
        int b = bb - 1536;
        int ksc = b & 15, by = (b >> 4) & 3, c = b >> 6;
        const float* W = (c < KF) ? Mp + (size_t)c * DIN * DOUT
                                  : Mm + (size_t)(c - KF) * DIN * DOUT;
        int o0 = by * 128, d0 = ksc * 32;
        for (int e = tid; e < 32 * 128; e += 256) {
            int dd = e >> 7, oo = e & 127;
            s[dd][oo] = W[(size_t)(d0 + dd) * DOUT + o0 + oo];
        }
        __syncthreads();
        __half2* dst = reinterpret_cast<__half2*>(g_WF + (size_t)b * 2048);
        for (int u = tid; u < 2048; u += 256) {
            int m, k; frag_decode(u, m, k);
            dst[u] = __halves2half2(__float2half_rn(s[k][m]), __float2half_rn(s[k + 1][m]));
        }
    } else if (bb < 5120) {
        // x paired-B-frags (gemm1 B): uint4 idx = (ksc*256 + tfrag)*32 + lane
        int idx = (bb - 4608) * 256 + tid;
        int lane = idx & 31, tfrag = (idx >> 5) & 255, ksc = idx >> 13;
        int t = tfrag * 8 + (lane >> 2);
        uint32_t comp[4];
        #pragma unroll
        for (int cI = 0; cI < 4; ++cI) {
            int kf = cI >> 1, reg = cI & 1;
            int d = ksc * 32 + kf * 16 + reg * 8 + (lane & 3) * 2;
            __half2 v = __floats2half2_rn(x[(size_t)t * DIN + d], x[(size_t)t * DIN + d + 1]);
            comp[cI] = *reinterpret_cast<uint32_t*>(&v);
        }
        g_xBF[idx] = make_uint4(comp[0], comp[1], comp[2], comp[3]);
    } else {
        // AR-weight paired-B-frags: uint4 idx = ((tau*16+ksc)*64 + nfrag)*32 + lane
        int idx = (bb - 5120) * 256 + tid;
        int lane = idx & 31, nfrag = (idx >> 5) & 63, ksc = (idx >> 11) & 15, tau = idx >> 15;
        int o = nfrag * 8 + (lane >> 2);
        uint32_t comp[4];
        #pragma unroll
        for (int cI = 0; cI < 4; ++cI) {
            int kf = cI >> 1, reg = cI & 1;
            int d = ksc * 32 + kf * 16 + reg * 8 + (lane & 3) * 2;
            __half2 v = __floats2half2_rn(M[((size_t)o * DIN + d) * KU + tau],
                                          M[((size_t)o * DIN + d + 1) * KU + tau]);
            comp[cI] = *reinterpret_cast<uint32_t*>(&v);
        }
        g_MF[idx] = make_uint4(comp[0], comp[1], comp[2], comp[3]);
    }
}

// ------- GEMM1: all-register-direct + L1 prefetch of chunk k+2 -------
__global__ void __launch_bounds__(NT, 2) gemm1_kernel() {
    const int tid = threadIdx.x;
    const int warp = tid >> 5, lane = tid & 31;
    const int mbase = (warp >> 2) * 64, nbase = (warp & 3) * 32;
    const int m16b = mbase >> 4;
    const int tx = blockIdx.x, by = blockIdx.y, c = blockIdx.z;
    const int o0 = by * 128;

    const uint4* abase = reinterpret_cast<const uint4*>(g_WF) + (size_t)(c * 4 + by) * 16 * 512;
    const int tf0 = tx * 16 + (nbase >> 3);

    float acc[4][4][4];
    #pragma unroll
    for (int i = 0; i < 4; ++i)
        #pragma unroll
        for (int j = 0; j < 4; ++j)
            #pragma unroll
            for (int e = 0; e < 4; ++e) acc[i][j][e] = 0.f;

    uint4 areg[2][4];
    uint4 breg[4];
    auto loadA = [&](int ksc) {
        const uint4* ap = abase + ksc * 512;
        #pragma unroll
        for (int kf = 0; kf < 2; ++kf)
            #pragma unroll
            for (int mf = 0; mf < 4; ++mf)
                areg[kf][mf] = ap[(m16b + mf) * 64 + kf * 32 + lane];
    };
    auto loadB = [&](int ksc) {
        #pragma unroll
        for (int nf = 0; nf < 4; ++nf)
            breg[nf] = g_xBF[(size_t)(ksc * 256 + tf0 + nf) * 32 + lane];
    };
    auto prefetch = [&](int ksc) {
        pfL1(abase + ksc * 512 + m16b * 64 + lane * 8);          // warp's 4KB A region
        pfL1(&g_xBF[(size_t)(ksc * 256 + tf0) * 32] + (lane & 15) * 8); // warp's 2KB B region
    };

    loadA(0); loadB(0);
    prefetch(1);
    for (int k = 0; k < 16; k++) {
        #pragma unroll
        for (int kf = 0; kf < 2; ++kf)
            #pragma unroll
            for (int mf = 0; mf < 4; ++mf)
                #pragma unroll
                for (int nf = 0; nf < 4; ++nf)
                    mma168(acc[mf][nf], reinterpret_cast<const uint32_t*>(&areg[kf][mf]),
                           reinterpret_cast<const uint32_t*>(&breg[nf]) + kf * 2);
        if (k + 1 < 16) {
            loadA(k + 1); loadB(k + 1);
            if (k + 2 < 16) prefetch(k + 2);
        }
    }

    const int tc = tx * 4 + (warp & 3);
    #pragma unroll
    for (int mf = 0; mf < 4; ++mf) {
        int nfr = (o0 + mbase + mf * 16) >> 3;
        uint32_t lo[4], hi[4];
        #pragma unroll
        for (int nf = 0; nf < 4; ++nf) {
            __half2 l = __floats2half2_rn(acc[mf][nf][0], acc[mf][nf][1]);
            __half2 h = __floats2half2_rn(acc[mf][nf][2], acc[mf][nf][3]);
            lo[nf] = *reinterpret_cast<uint32_t*>(&l);
            hi[nf] = *reinterpret_cast<uint32_t*>(&h);
        }
        g_ZF[(size_t)((c * 64 + tc) * 64 + nfr) * 32 + lane]     = make_uint4(lo[0], lo[1], lo[2], lo[3]);
        g_ZF[(size_t)((c * 64 + tc) * 64 + nfr + 1) * 32 + lane] = make_uint4(hi[0], hi[1], hi[2], hi[3]);
    }
}

// -- GEMM2: unchanged from R15 (best): single-buffer + L1 prefetch dist-1 --
__global__ void __launch_bounds__(NT, 2) gemm2_kernel() {
    const int tid = threadIdx.x;
    const int warp = tid >> 5, lane = tid & 31;
    const int lg = lane >> 2, t4 = lane & 3;
    const int mbase = (warp >> 2) * 64, nbase = (warp & 3) * 32;
    const int m16b = mbase >> 4;

    const int bx = (int)blockIdx.x;
    int i = 15;
    #pragma unroll
    for (int ii = 0; ii < 16; ++ii)
        if (bx >= c_OFF[ii] && bx < c_OFF[ii] + 4 * c_SP[ii]) i = ii;
    const int w = bx - c_OFF[i];
    const int SP = c_SP[i];
    const int ot = w % 4, sp = w / 4;
    const int t0 = i * 128, o0 = ot * 128;
    const int per = (i + 1) * 4, nconv = NC * per, ntot = nconv + KU * (DIN / 32);
    const int NCH = (ntot - sp + SP - 1) / SP;
    const int nfr0 = (o0 >> 3) + (nbase >> 3);

    float acc[4][4][4];
    #pragma unroll
    for (int a0 = 0; a0 < 4; ++a0)
        #pragma unroll
        for (int b0 = 0; b0 < 4; ++b0)
            #pragma unroll
            for (int e = 0; e < 4; ++e) acc[a0][b0][e] = 0.f;

    int q = sp;
    int cch = sp / per;
    int rm = sp - cch * per;

    uint4 areg[2][4];
    uint4 breg[4];
    auto chunkPtrs = [&](const uint4*& ap, const uint4*& bp) {
        if (q < nconv) {
            int j = rm >> 2, ks = rm & 3;
            ap = reinterpret_cast<const uint4*>(g_ToepF) +
                 (size_t)((cch * 16 + (i - j)) * 4 + ks) * 512;
            bp = g_ZF + (size_t)((cch * 64 + j * 4 + ks) * 64 + nfr0) * 32;
        } else {
            int r = q - nconv, tau = r >> 4, ksc = r & 15;
            ap = reinterpret_cast<const uint4*>(g_xF) +
                 (size_t)((tau * 16 + i) * 16 + ksc) * 512;
            bp = g_MF + (size_t)((tau * 16 + ksc) * 64 + nfr0) * 32;
        }
    };
    auto advance = [&]() {
        q += SP;
        rm += SP;
        if (rm >= per) { rm -= per; cch++; }
    };
    auto loadChunk = [&]() {
        const uint4* ap;
        const uint4* bp;
        chunkPtrs(ap, bp);
        #pragma unroll
        for (int kf = 0; kf < 2; ++kf)
            #pragma unroll
            for (int mf = 0; mf < 4; ++mf)
                areg[kf][mf] = ap[(m16b + mf) * 64 + kf * 32 + lane];
        #pragma unroll
        for (int nf = 0; nf < 4; ++nf)
            breg[nf] = bp[(size_t)nf * 32 + lane];
        advance();
        if (q < ntot) {
            const uint4* pa;
            const uint4* pb;
            chunkPtrs(pa, pb);
            pfL1(pa + m16b * 64 + lane * 8);
            pfL1(pb + (lane & 15) * 8);
        }
    };

    loadChunk();
    for (int k = 0; k < NCH; k++) {
        #pragma unroll
        for (int kf = 0; kf < 2; ++kf)
            #pragma unroll
            for (int mf = 0; mf < 4; ++mf)
                #pragma unroll
                for (int nf = 0; nf < 4; ++nf)
                    mma168(acc[mf][nf], reinterpret_cast<const uint32_t*>(&areg[kf][mf]),
                           reinterpret_cast<const uint32_t*>(&breg[nf]) + kf * 2);
        if (k + 1 < NCH) loadChunk();
    }

    float* P = g_part + (size_t)sp * T * DOUT;
    #pragma unroll
    for (int mf = 0; mf < 4; ++mf) {
        int r0 = t0 + mbase + mf * 16 + lg;
        #pragma unroll
        for (int nf = 0; nf < 4; ++nf) {
            int cc = o0 + nbase + nf * 8 + 2 * t4;
            *(float2*)(P + (size_t)r0 * DOUT + cc)       = make_float2(acc[mf][nf][0], acc[mf][nf][1]);
            *(float2*)(P + (size_t)(r0 + 8) * DOUT + cc) = make_float2(acc[mf][nf][2], acc[mf][nf][3]);
        }
    }
}

// ---------------- reduce split-K partials (tile i has c_SP[i] planes) ----------------
__global__ void reduce_kernel(float* __restrict__ out) {
    size_t idx = (size_t)(blockIdx.x * blockDim.x + threadIdx.x) * 4;
    int t = (int)(idx / DOUT);
    int np = c_SP[t >> 7];
    float4 s = make_float4(0.f, 0.f, 0.f, 0.f);
    for (int p = 0; p < np; ++p) {
        float4 v = *(const float4*)(g_part + (size_t)p * T * DOUT + idx);
        s.x += v.x; s.y += v.y; s.z += v.z; s.w += v.w;
    }
    *(float4*)(out + idx) = s;
}

// ---------------- entry ----------------
extern "C" void kernel_launch(void* const* d_in, const int* in_sizes, int n_in,
                              void* d_out, int out_size) {
    const float* x   = (const float*)d_in[0];
    const float* phi = (const float*)d_in[1];
    const float* M   = (const float*)d_in[2];
    const float* Mp  = (const float*)d_in[3];
    const float* Mm  = (const float*)d_in[4];
    float* out = (float*)d_out;

    prep_all<<<5504, NT>>>(x, phi, M, Mp, Mm);
    gemm1_kernel<<<dim3(16, 4, NC), NT>>>();
    gemm2_kernel<<<GRID2, NT>>>();
    reduce_kernel<<<(T * DOUT / 4 + 255) / 256, 256>>>(out);
}